// round 1
// baseline (speedup 1.0000x reference)
#include <cuda_runtime.h>

#define NUM_EXPERTS   3
#define INPUT_DIM     1024
#define HIDDEN_DIM    4096
#define OUTPUT_DIM    1024
#define ROUTER_HIDDEN 128
#define BATCH         8192

// ---------------- device scratch (allowed: __device__ globals) ----------------
__device__ float g_RH[BATCH * ROUTER_HIDDEN];           // 4 MB router hidden
__device__ float g_H[(size_t)BATCH * HIDDEN_DIM];       // 128 MB expert hidden (compact order)
__device__ int   g_selected[BATCH];
__device__ int   g_counts[NUM_EXPERTS];
__device__ int   g_cursor[NUM_EXPERTS];
__device__ int   g_offsets[NUM_EXPERTS + 1];
__device__ int   g_perm[BATCH];

// ---------------- small kernels ----------------
__global__ void init_kernel() {
    int t = threadIdx.x;
    if (t < NUM_EXPERTS) { g_counts[t] = 0; g_cursor[t] = 0; }
}

// one warp per token: logits = RH[t] @ rw2 + rb2 ; argmax (first max) ; count
__global__ void router_logits_kernel(const float* __restrict__ rw2,
                                     const float* __restrict__ rb2) {
    int gwarp = (blockIdx.x * blockDim.x + threadIdx.x) >> 5;
    int lane  = threadIdx.x & 31;
    if (gwarp >= BATCH) return;

    float4 rh4 = *(const float4*)(g_RH + (size_t)gwarp * ROUTER_HIDDEN + lane * 4);
    float p0 = 0.f, p1 = 0.f, p2 = 0.f;
    const float* h = (const float*)&rh4;
#pragma unroll
    for (int j = 0; j < 4; j++) {
        int hidx = lane * 4 + j;
        p0 += h[j] * rw2[hidx * 3 + 0];
        p1 += h[j] * rw2[hidx * 3 + 1];
        p2 += h[j] * rw2[hidx * 3 + 2];
    }
#pragma unroll
    for (int s = 16; s > 0; s >>= 1) {
        p0 += __shfl_xor_sync(0xFFFFFFFFu, p0, s);
        p1 += __shfl_xor_sync(0xFFFFFFFFu, p1, s);
        p2 += __shfl_xor_sync(0xFFFFFFFFu, p2, s);
    }
    if (lane == 0) {
        float l0 = p0 + rb2[0], l1 = p1 + rb2[1], l2 = p2 + rb2[2];
        int sel = 0; float best = l0;
        if (l1 > best) { best = l1; sel = 1; }
        if (l2 > best) { best = l2; sel = 2; }
        g_selected[gwarp] = sel;
        atomicAdd(&g_counts[sel], 1);
    }
}

__global__ void offsets_kernel(float* __restrict__ stats_out) {
    // single thread
    int o = 0;
#pragma unroll
    for (int e = 0; e < NUM_EXPERTS; e++) {
        g_offsets[e] = o;
        if (stats_out) stats_out[e] = (float)g_counts[e];
        o += g_counts[e];
    }
    g_offsets[NUM_EXPERTS] = o;
}

__global__ void perm_kernel() {
    int t = blockIdx.x * blockDim.x + threadIdx.x;
    if (t >= BATCH) return;
    int e = g_selected[t];
    int pos = g_offsets[e] + atomicAdd(&g_cursor[e], 1);
    g_perm[pos] = t;
}

// ---------------- 128x128 fp32 SGEMM (BK=8, 8x8 microtile, 256 threads) ----------------
// SEG:       blockIdx.z = expert segment; row range from g_offsets
// GATHER_A:  A row index via g_perm (gather input rows)
// RELU:      relu epilogue
// SCATTER_C: C row index via g_perm (scatter output rows)
#define BM 128
#define BN 128
#define BK 8
#define TM 8
#define TN 8

template <bool SEG, bool GATHER_A, bool RELU, bool SCATTER_C>
__global__ __launch_bounds__(256, 2)
void gemm_kernel(const float* __restrict__ Abase, const float* __restrict__ Wbase,
                 const float* __restrict__ biasbase, float* __restrict__ Cbase,
                 int N, int K, int lda, int ldc) {
    int e = SEG ? blockIdx.z : 0;
    int off = 0, cnt;
    if (SEG) { off = g_offsets[e]; cnt = g_offsets[e + 1] - off; }
    else     { cnt = BATCH; }

    int tileM = blockIdx.y * BM;
    if (tileM >= cnt) return;
    int bn = blockIdx.x * BN;

    const float* W    = Wbase    + (SEG ? (size_t)e * K * N : 0);
    const float* bias = biasbase + (SEG ? (size_t)e * N     : 0);

    __shared__ __align__(16) float As[BK][BM];
    __shared__ __align__(16) float Bs[BK][BN];

    int tid = threadIdx.x;

    // A tile load mapping: 128 rows x 8 k, one float4 per thread
    int arow = tid >> 1;
    int akq  = (tid & 1) * 4;
    int am   = tileM + arow;
    bool avalid = (am < cnt);
    const float* Aptr = nullptr;
    if (avalid) {
        int grow;
        if (SEG) grow = GATHER_A ? g_perm[off + am] : (off + am);
        else     grow = am;
        Aptr = Abase + (size_t)grow * lda;
    }

    // B tile load mapping: 8 k x 128 n, one float4 per thread
    int brow = tid >> 5;
    int bcol = (tid & 31) * 4;

    int trow = (tid >> 4) * TM;   // 0..120
    int tcol = (tid & 15) * TN;   // 0..120

    float acc[TM][TN];
#pragma unroll
    for (int i = 0; i < TM; i++)
#pragma unroll
        for (int j = 0; j < TN; j++) acc[i][j] = 0.f;

    for (int k0 = 0; k0 < K; k0 += BK) {
        float4 a4 = avalid ? *(const float4*)(Aptr + k0 + akq)
                           : make_float4(0.f, 0.f, 0.f, 0.f);
        As[akq + 0][arow] = a4.x;
        As[akq + 1][arow] = a4.y;
        As[akq + 2][arow] = a4.z;
        As[akq + 3][arow] = a4.w;

        float4 b4 = *(const float4*)(W + (size_t)(k0 + brow) * N + bn + bcol);
        *(float4*)&Bs[brow][bcol] = b4;

        __syncthreads();
#pragma unroll
        for (int kk = 0; kk < BK; kk++) {
            float ar[TM], br[TN];
            *(float4*)&ar[0] = *(const float4*)&As[kk][trow];
            *(float4*)&ar[4] = *(const float4*)&As[kk][trow + 4];
            *(float4*)&br[0] = *(const float4*)&Bs[kk][tcol];
            *(float4*)&br[4] = *(const float4*)&Bs[kk][tcol + 4];
#pragma unroll
            for (int i = 0; i < TM; i++)
#pragma unroll
                for (int j = 0; j < TN; j++)
                    acc[i][j] = fmaf(ar[i], br[j], acc[i][j]);
        }
        __syncthreads();
    }

    // epilogue
#pragma unroll
    for (int i = 0; i < TM; i++) {
        int m = tileM + trow + i;
        if (m >= cnt) continue;
        int crow;
        if (SEG) crow = SCATTER_C ? g_perm[off + m] : (off + m);
        else     crow = m;
        float* Crow = Cbase + (size_t)crow * ldc + bn + tcol;
#pragma unroll
        for (int j = 0; j < TN; j++) {
            float v = acc[i][j] + bias[bn + tcol + j];
            if (RELU) v = fmaxf(v, 0.f);
            Crow[j] = v;
        }
    }
}

// ---------------- launch ----------------
extern "C" void kernel_launch(void* const* d_in, const int* in_sizes, int n_in,
                              void* d_out, int out_size) {
    const float* x   = (const float*)d_in[0];
    const float* rw1 = (const float*)d_in[1];
    const float* rb1 = (const float*)d_in[2];
    const float* rw2 = (const float*)d_in[3];
    const float* rb2 = (const float*)d_in[4];
    const float* ew1 = (const float*)d_in[5];
    const float* eb1 = (const float*)d_in[6];
    const float* ew2 = (const float*)d_in[7];
    const float* eb2 = (const float*)d_in[8];
    float* out = (float*)d_out;

    float *pRH = nullptr, *pH = nullptr;
    cudaGetSymbolAddress((void**)&pRH, g_RH);
    cudaGetSymbolAddress((void**)&pH,  g_H);

    float* stats = nullptr;
    if (out_size >= BATCH * OUTPUT_DIM + NUM_EXPERTS)
        stats = out + (size_t)BATCH * OUTPUT_DIM;

    init_kernel<<<1, 32>>>();

    // Router layer 1: RH = relu(x @ rw1 + rb1)   [8192 x 128], K=1024
    gemm_kernel<false, false, true, false>
        <<<dim3(ROUTER_HIDDEN / BN, BATCH / BM, 1), 256>>>(
            x, rw1, rb1, pRH, ROUTER_HIDDEN, INPUT_DIM, INPUT_DIM, ROUTER_HIDDEN);

    // Router layer 2 + argmax + counts
    router_logits_kernel<<<(BATCH * 32 + 255) / 256, 256>>>(rw2, rb2);

    // Offsets (+ routing_stats output) and permutation
    offsets_kernel<<<1, 1>>>(stats);
    perm_kernel<<<(BATCH + 255) / 256, 256>>>();

    // Expert layer 1: H = relu(gather(x) @ W1_e + b1_e)   per-expert segments
    gemm_kernel<true, true, true, false>
        <<<dim3(HIDDEN_DIM / BN, BATCH / BM, NUM_EXPERTS), 256>>>(
            x, ew1, eb1, pH, HIDDEN_DIM, INPUT_DIM, INPUT_DIM, HIDDEN_DIM);

    // Expert layer 2: out[perm] = H @ W2_e + b2_e
    gemm_kernel<true, false, false, true>
        <<<dim3(OUTPUT_DIM / BN, BATCH / BM, NUM_EXPERTS), 256>>>(
            pH, ew2, eb2, out, OUTPUT_DIM, HIDDEN_DIM, HIDDEN_DIM, OUTPUT_DIM);
}

// round 2
// speedup vs baseline: 1.4846x; 1.4846x over previous
#include <cuda_runtime.h>
#include <cstdint>

#define NUM_EXPERTS   3
#define INPUT_DIM     1024
#define HIDDEN_DIM    4096
#define OUTPUT_DIM    1024
#define ROUTER_HIDDEN 128
#define BATCH         8192

// ---------------- device scratch ----------------
__device__ float g_RH[BATCH * ROUTER_HIDDEN];
__device__ float g_H[(size_t)BATCH * HIDDEN_DIM];
__device__ int   g_selected[BATCH];
__device__ int   g_counts[NUM_EXPERTS];
__device__ int   g_cursor[NUM_EXPERTS];
__device__ int   g_offsets[NUM_EXPERTS + 1];
__device__ int   g_perm[BATCH];

// ---------------- small kernels ----------------
__global__ void init_kernel() {
    int t = threadIdx.x;
    if (t < NUM_EXPERTS) { g_counts[t] = 0; g_cursor[t] = 0; }
}

__global__ void router_logits_kernel(const float* __restrict__ rw2,
                                     const float* __restrict__ rb2) {
    int gwarp = (blockIdx.x * blockDim.x + threadIdx.x) >> 5;
    int lane  = threadIdx.x & 31;
    if (gwarp >= BATCH) return;

    float4 rh4 = *(const float4*)(g_RH + (size_t)gwarp * ROUTER_HIDDEN + lane * 4);
    float p0 = 0.f, p1 = 0.f, p2 = 0.f;
    const float* h = (const float*)&rh4;
#pragma unroll
    for (int j = 0; j < 4; j++) {
        int hidx = lane * 4 + j;
        p0 += h[j] * rw2[hidx * 3 + 0];
        p1 += h[j] * rw2[hidx * 3 + 1];
        p2 += h[j] * rw2[hidx * 3 + 2];
    }
#pragma unroll
    for (int s = 16; s > 0; s >>= 1) {
        p0 += __shfl_xor_sync(0xFFFFFFFFu, p0, s);
        p1 += __shfl_xor_sync(0xFFFFFFFFu, p1, s);
        p2 += __shfl_xor_sync(0xFFFFFFFFu, p2, s);
    }
    if (lane == 0) {
        float l0 = p0 + rb2[0], l1 = p1 + rb2[1], l2 = p2 + rb2[2];
        int sel = 0; float best = l0;
        if (l1 > best) { best = l1; sel = 1; }
        if (l2 > best) { best = l2; sel = 2; }
        g_selected[gwarp] = sel;
        atomicAdd(&g_counts[sel], 1);
    }
}

__global__ void offsets_kernel(float* __restrict__ stats_out) {
    int o = 0;
#pragma unroll
    for (int e = 0; e < NUM_EXPERTS; e++) {
        g_offsets[e] = o;
        if (stats_out) stats_out[e] = (float)g_counts[e];
        o += g_counts[e];
    }
    g_offsets[NUM_EXPERTS] = o;
}

__global__ void perm_kernel() {
    int t = blockIdx.x * blockDim.x + threadIdx.x;
    if (t >= BATCH) return;
    int e = g_selected[t];
    int pos = g_offsets[e] + atomicAdd(&g_cursor[e], 1);
    g_perm[pos] = t;
}

// ---------------- fp32 SIMT GEMM (router layer 1 only) ----------------
#define BM 128
#define BN 128
#define BK 8
#define TM 8
#define TN 8

__global__ __launch_bounds__(256, 2)
void router_gemm_kernel(const float* __restrict__ Abase, const float* __restrict__ Wbase,
                        const float* __restrict__ biasbase, float* __restrict__ Cbase,
                        int N, int K, int lda, int ldc) {
    int cnt = BATCH;
    int tileM = blockIdx.y * BM;
    int bn = blockIdx.x * BN;

    __shared__ __align__(16) float As[BK][BM];
    __shared__ __align__(16) float Bs[BK][BN];

    int tid = threadIdx.x;
    int arow = tid >> 1;
    int akq  = (tid & 1) * 4;
    int am   = tileM + arow;
    const float* Aptr = Abase + (size_t)am * lda;

    int brow = tid >> 5;
    int bcol = (tid & 31) * 4;

    int trow = (tid >> 4) * TM;
    int tcol = (tid & 15) * TN;

    float acc[TM][TN];
#pragma unroll
    for (int i = 0; i < TM; i++)
#pragma unroll
        for (int j = 0; j < TN; j++) acc[i][j] = 0.f;

    for (int k0 = 0; k0 < K; k0 += BK) {
        float4 a4 = *(const float4*)(Aptr + k0 + akq);
        As[akq + 0][arow] = a4.x;
        As[akq + 1][arow] = a4.y;
        As[akq + 2][arow] = a4.z;
        As[akq + 3][arow] = a4.w;

        float4 b4 = *(const float4*)(Wbase + (size_t)(k0 + brow) * N + bn + bcol);
        *(float4*)&Bs[brow][bcol] = b4;

        __syncthreads();
#pragma unroll
        for (int kk = 0; kk < BK; kk++) {
            float ar[TM], br[TN];
            *(float4*)&ar[0] = *(const float4*)&As[kk][trow];
            *(float4*)&ar[4] = *(const float4*)&As[kk][trow + 4];
            *(float4*)&br[0] = *(const float4*)&Bs[kk][tcol];
            *(float4*)&br[4] = *(const float4*)&Bs[kk][tcol + 4];
#pragma unroll
            for (int i = 0; i < TM; i++)
#pragma unroll
                for (int j = 0; j < TN; j++)
                    acc[i][j] = fmaf(ar[i], br[j], acc[i][j]);
        }
        __syncthreads();
    }

#pragma unroll
    for (int i = 0; i < TM; i++) {
        int m = tileM + trow + i;
        if (m >= cnt) continue;
        float* Crow = Cbase + (size_t)m * ldc + bn + tcol;
#pragma unroll
        for (int j = 0; j < TN; j++) {
            float v = acc[i][j] + biasbase[bn + tcol + j];
            Crow[j] = fmaxf(v, 0.f);
        }
    }
}

// ---------------- tf32 tensor-core grouped GEMM ----------------
// Block tile 128x128x32, 4 warps (2x2) of 64x64 each, mma.m16n8k8.tf32,
// fragment-packed shared memory, double buffered, 1 sync per k-tile.

__device__ __forceinline__ uint32_t f2tf32(float x) {
    uint32_t r;
    asm("cvt.rna.tf32.f32 %0, %1;" : "=r"(r) : "f"(x));
    return r;
}

template<bool GATHER_A, bool RELU, bool SCATTER_C>
__global__ __launch_bounds__(128, 1)
void tf32_gemm(const float* __restrict__ Abase, const float* __restrict__ Wbase,
               const float* __restrict__ biasbase, float* __restrict__ Cbase,
               int N, int K, int lda, int ldc) {
    extern __shared__ uint32_t sm[];   // [2][4096] A words + [2][4096] B words = 64KB

    const int e = blockIdx.z;
    const int off = g_offsets[e];
    const int cnt = g_offsets[e + 1] - off;
    const int tileM = blockIdx.y * 128;
    if (tileM >= cnt) return;
    const int bn = blockIdx.x * 128;

    const float* W    = Wbase    + (size_t)e * K * N;
    const float* bias = biasbase + (size_t)e * N;

    const int t = threadIdx.x;
    const int wid = t >> 5, lane = t & 31;
    const int warpRow = wid >> 1, warpCol = wid & 1;

    // ---- A gmem mapping: tile rows j*16 + (t>>3), col4 = t&7 ----
    const int mrb  = t >> 3;      // 0..15
    const int col4 = t & 7;       // 0..7
    const float* arow[8];
    bool avalid[8];
#pragma unroll
    for (int j = 0; j < 8; j++) {
        int gm = tileM + j * 16 + mrb;
        bool v = gm < cnt;
        avalid[j] = v;
        int grow = 0;
        if (v) grow = GATHER_A ? g_perm[off + gm] : (off + gm);
        arow[j] = Abase + (size_t)grow * lda;
    }
    // A STS constants
    const int a_ks = col4 >> 1, a_kh = col4 & 1;
    const int a_g  = mrb & 7,   a_mh = mrb >> 3;

    // ---- B gmem mapping: k = j*4 + wid, n4 = lane-across-warp = t&31 ----
    const int n4 = t & 31;

    float4 ra[8], rb[8];
    float acc[4][8][4];
#pragma unroll
    for (int i = 0; i < 4; i++)
#pragma unroll
        for (int j = 0; j < 8; j++)
#pragma unroll
            for (int q = 0; q < 4; q++) acc[i][j][q] = 0.f;

    const int KT = K / 32;

    // prologue load k-tile 0
#pragma unroll
    for (int j = 0; j < 8; j++)
        ra[j] = avalid[j] ? *(const float4*)(arow[j] + col4 * 4)
                          : make_float4(0.f, 0.f, 0.f, 0.f);
#pragma unroll
    for (int j = 0; j < 8; j++) {
        int k = j * 4 + wid;
        rb[j] = *(const float4*)(W + (size_t)k * N + bn + n4 * 4);
    }

    for (int kt = 0; kt < KT; kt++) {
        // ---- STS into buffer kt&1 (fragment-packed, tf32-converted) ----
        {
            uint32_t* As = sm + (kt & 1) * 4096;
            uint32_t* Bs = sm + 8192 + (kt & 1) * 4096;
#pragma unroll
            for (int j = 0; j < 8; j++) {
                const float* v = (const float*)&ra[j];
                int base = ((a_ks * 8 + j) * 32 + a_g * 4) * 4 + a_kh * 2 + a_mh;
#pragma unroll
                for (int i = 0; i < 4; i++)
                    As[base + i * 4] = f2tf32(v[i]);
            }
#pragma unroll
            for (int j = 0; j < 8; j++) {
                int k = j * 4 + wid;
                int ks = k >> 3, tigb = k & 3, r = (k >> 2) & 1;
                const float* v = (const float*)&rb[j];
#pragma unroll
                for (int i = 0; i < 4; i++) {
                    int g = (n4 & 1) * 4 + i;
                    int nt = n4 >> 1;
                    Bs[((ks * 16 + nt) * 32 + g * 4 + tigb) * 2 + r] = f2tf32(v[i]);
                }
            }
        }
        __syncthreads();

        // ---- prefetch next k-tile (overlaps with compute) ----
        if (kt + 1 < KT) {
            int k0 = (kt + 1) * 32;
#pragma unroll
            for (int j = 0; j < 8; j++)
                ra[j] = avalid[j] ? *(const float4*)(arow[j] + k0 + col4 * 4)
                                  : make_float4(0.f, 0.f, 0.f, 0.f);
#pragma unroll
            for (int j = 0; j < 8; j++) {
                int k = j * 4 + wid;
                rb[j] = *(const float4*)(W + (size_t)(k0 + k) * N + bn + n4 * 4);
            }
        }

        // ---- compute on buffer kt&1 ----
        {
            const uint32_t* As = sm + (kt & 1) * 4096;
            const uint32_t* Bs = sm + 8192 + (kt & 1) * 4096;
#pragma unroll
            for (int ks = 0; ks < 4; ks++) {
                uint32_t af[4][4];
#pragma unroll
                for (int mtl = 0; mtl < 4; mtl++) {
                    uint4 v = *(const uint4*)(As + ((ks * 8 + warpRow * 4 + mtl) * 32 + lane) * 4);
                    af[mtl][0] = v.x; af[mtl][1] = v.y; af[mtl][2] = v.z; af[mtl][3] = v.w;
                }
#pragma unroll
                for (int ntl = 0; ntl < 8; ntl++) {
                    uint2 bv = *(const uint2*)(Bs + ((ks * 16 + warpCol * 8 + ntl) * 32 + lane) * 2);
#pragma unroll
                    for (int mtl = 0; mtl < 4; mtl++) {
                        asm volatile(
                            "mma.sync.aligned.m16n8k8.row.col.f32.tf32.tf32.f32 "
                            "{%0,%1,%2,%3}, {%4,%5,%6,%7}, {%8,%9}, {%0,%1,%2,%3};\n"
                            : "+f"(acc[mtl][ntl][0]), "+f"(acc[mtl][ntl][1]),
                              "+f"(acc[mtl][ntl][2]), "+f"(acc[mtl][ntl][3])
                            : "r"(af[mtl][0]), "r"(af[mtl][1]), "r"(af[mtl][2]), "r"(af[mtl][3]),
                              "r"(bv.x), "r"(bv.y));
                    }
                }
            }
        }
    }

    // ---- epilogue: bias (+relu), scatter/compact store ----
    const int cbase = bn + warpCol * 64 + (lane & 3) * 2;
#pragma unroll
    for (int mtl = 0; mtl < 4; mtl++) {
        int r0 = tileM + warpRow * 64 + mtl * 16 + (lane >> 2);
#pragma unroll
        for (int half = 0; half < 2; half++) {
            int gm = r0 + half * 8;
            if (gm >= cnt) continue;
            int crow = SCATTER_C ? g_perm[off + gm] : (off + gm);
            float* cp = Cbase + (size_t)crow * ldc + cbase;
#pragma unroll
            for (int ntl = 0; ntl < 8; ntl++) {
                float v0 = acc[mtl][ntl][half * 2 + 0] + bias[cbase + ntl * 8 + 0];
                float v1 = acc[mtl][ntl][half * 2 + 1] + bias[cbase + ntl * 8 + 1];
                if (RELU) { v0 = fmaxf(v0, 0.f); v1 = fmaxf(v1, 0.f); }
                float2 o; o.x = v0; o.y = v1;
                *(float2*)(cp + ntl * 8) = o;
            }
        }
    }
}

// ---------------- launch ----------------
extern "C" void kernel_launch(void* const* d_in, const int* in_sizes, int n_in,
                              void* d_out, int out_size) {
    const float* x   = (const float*)d_in[0];
    const float* rw1 = (const float*)d_in[1];
    const float* rb1 = (const float*)d_in[2];
    const float* rw2 = (const float*)d_in[3];
    const float* rb2 = (const float*)d_in[4];
    const float* ew1 = (const float*)d_in[5];
    const float* eb1 = (const float*)d_in[6];
    const float* ew2 = (const float*)d_in[7];
    const float* eb2 = (const float*)d_in[8];
    float* out = (float*)d_out;

    float *pRH = nullptr, *pH = nullptr;
    cudaGetSymbolAddress((void**)&pRH, g_RH);
    cudaGetSymbolAddress((void**)&pH,  g_H);

    float* stats = nullptr;
    if (out_size >= BATCH * OUTPUT_DIM + NUM_EXPERTS)
        stats = out + (size_t)BATCH * OUTPUT_DIM;

    cudaFuncSetAttribute(tf32_gemm<true,  true,  false>,
                         cudaFuncAttributeMaxDynamicSharedMemorySize, 65536);
    cudaFuncSetAttribute(tf32_gemm<false, false, true>,
                         cudaFuncAttributeMaxDynamicSharedMemorySize, 65536);

    init_kernel<<<1, 32>>>();

    // Router layer 1 (fp32 — keep routing decisions bit-stable)
    router_gemm_kernel<<<dim3(ROUTER_HIDDEN / BN, BATCH / BM, 1), 256>>>(
        x, rw1, rb1, pRH, ROUTER_HIDDEN, INPUT_DIM, INPUT_DIM, ROUTER_HIDDEN);

    router_logits_kernel<<<(BATCH * 32 + 255) / 256, 256>>>(rw2, rb2);
    offsets_kernel<<<1, 1>>>(stats);
    perm_kernel<<<(BATCH + 255) / 256, 256>>>();

    // Expert layer 1: H = relu(gather(x) @ W1_e + b1_e)  (tf32 tensor cores)
    tf32_gemm<true, true, false>
        <<<dim3(HIDDEN_DIM / 128, BATCH / 128, NUM_EXPERTS), 128, 65536>>>(
            x, ew1, eb1, pH, HIDDEN_DIM, INPUT_DIM, INPUT_DIM, HIDDEN_DIM);

    // Expert layer 2: out[perm] = H @ W2_e + b2_e  (tf32 tensor cores)
    tf32_gemm<false, false, true>
        <<<dim3(OUTPUT_DIM / 128, BATCH / 128, NUM_EXPERTS), 128, 65536>>>(
            pH, ew2, eb2, out, OUTPUT_DIM, HIDDEN_DIM, HIDDEN_DIM, OUTPUT_DIM);
}